// round 6
// baseline (speedup 1.0000x reference)
#include <cuda_runtime.h>
#include <stdint.h>

#define N_ROWS 1024   // N
#define P_PIX  1024   // P
#define E_DIM  512    // ENC / TAG / LANG
#define A_DIM  256    // ATT

// Scratch
__device__ float g_att1 [P_PIX * A_DIM];    // (P, A)  enc@We^T + be
__device__ float g_att23[N_ROWS * A_DIM];   // (N, A)  dh@Wt^T + bt
__device__ float g_att3 [N_ROWS * A_DIM];   // (N, A)  lo@Wl^T + bl
__device__ float g_att  [N_ROWS * P_PIX];   // (N, P)

// ---- tf32 helpers ----
__device__ __forceinline__ uint32_t f2tf(float x) {
    uint32_t r; asm("cvt.rna.tf32.f32 %0, %1;" : "=r"(r) : "f"(x)); return r;
}

#define MMA_TF32(d, a, b)                                                   \
  asm("mma.sync.aligned.m16n8k8.row.col.f32.tf32.tf32.f32 "                 \
      "{%0,%1,%2,%3},{%4,%5,%6,%7},{%8,%9},{%0,%1,%2,%3};"                  \
      : "+f"(d[0]), "+f"(d[1]), "+f"(d[2]), "+f"(d[3])                      \
      : "r"(a[0]), "r"(a[1]), "r"(a[2]), "r"(a[3]), "r"(b[0]), "r"(b[1]))

// ---------------------------------------------------------------------------
// Kernel 1: tc_attproj — C = A @ W^T + bias, per z-slice (M=1024, N=256, K=512)
//   z=0: g_att1  = enc @ We^T + be
//   z=1: g_att23 = dh  @ Wt^T + bt
//   z=2: g_att3  = lo  @ Wl^T + bl
// Block 64x64, BK=32, 256 thr, warp tile 32m x 16n, 3x-TF32 split mma.
// ---------------------------------------------------------------------------
__global__ __launch_bounds__(256)
void tc_attproj(const float* __restrict__ enc, const float* __restrict__ We, const float* __restrict__ be,
                const float* __restrict__ dh,  const float* __restrict__ Wt, const float* __restrict__ bt,
                const float* __restrict__ lo,  const float* __restrict__ Wl, const float* __restrict__ bl)
{
    __shared__ uint32_t Ahi[32][68], Alo[32][68];
    __shared__ uint32_t Bhi[32][68], Blo[32][68];

    const int z = blockIdx.z;
    const float* A  = (z == 0) ? enc : (z == 1) ? dh : lo;
    const float* W  = (z == 0) ? We  : (z == 1) ? Wt : Wl;
    const float* bv = (z == 0) ? be  : (z == 1) ? bt : bl;
    float*       C  = (z == 0) ? g_att1 : (z == 1) ? g_att23 : g_att3;

    const int tid = threadIdx.x;
    const int m0  = blockIdx.y * 64;
    const int n0  = blockIdx.x * 64;

    const int am  = tid >> 2;          // 0..63
    const int akc = (tid & 3) * 8;     // {0,8,16,24}

    const int lane = tid & 31, wid = tid >> 5;
    const int wm = (wid >> 2) * 32;    // 0 / 32
    const int wn = (wid & 3) * 16;     // 0/16/32/48
    const int g = lane >> 2, t = lane & 3;

    float acc[2][2][4] = {};

    float4 apre[2], bpre[2];
    apre[0] = *(const float4*)&A[(m0 + am) * E_DIM + akc];
    apre[1] = *(const float4*)&A[(m0 + am) * E_DIM + akc + 4];
    bpre[0] = *(const float4*)&W[(n0 + am) * E_DIM + akc];
    bpre[1] = *(const float4*)&W[(n0 + am) * E_DIM + akc + 4];

    for (int k0 = 0; k0 < E_DIM; k0 += 32) {
        if (k0 > 0) __syncthreads();
        #pragma unroll
        for (int q = 0; q < 2; q++) {
            float av[4] = {apre[q].x, apre[q].y, apre[q].z, apre[q].w};
            float bw[4] = {bpre[q].x, bpre[q].y, bpre[q].z, bpre[q].w};
            #pragma unroll
            for (int j = 0; j < 4; j++) {
                uint32_t h = f2tf(av[j]);
                Ahi[akc + 4 * q + j][am] = h;
                Alo[akc + 4 * q + j][am] = f2tf(av[j] - __uint_as_float(h));
                uint32_t hb = f2tf(bw[j]);
                Bhi[akc + 4 * q + j][am] = hb;
                Blo[akc + 4 * q + j][am] = f2tf(bw[j] - __uint_as_float(hb));
            }
        }
        __syncthreads();

        if (k0 + 32 < E_DIM) {
            apre[0] = *(const float4*)&A[(m0 + am) * E_DIM + k0 + 32 + akc];
            apre[1] = *(const float4*)&A[(m0 + am) * E_DIM + k0 + 36 + akc];
            bpre[0] = *(const float4*)&W[(n0 + am) * E_DIM + k0 + 32 + akc];
            bpre[1] = *(const float4*)&W[(n0 + am) * E_DIM + k0 + 36 + akc];
        }

        #pragma unroll
        for (int ks = 0; ks < 4; ks++) {
            const int k8 = ks * 8;
            uint32_t Af[2][2][4];
            #pragma unroll
            for (int mf = 0; mf < 2; mf++) {
                int r = wm + mf * 16 + g;
                Af[mf][0][0] = Ahi[k8 + t][r];     Af[mf][0][1] = Ahi[k8 + t][r + 8];
                Af[mf][0][2] = Ahi[k8 + t + 4][r]; Af[mf][0][3] = Ahi[k8 + t + 4][r + 8];
                Af[mf][1][0] = Alo[k8 + t][r];     Af[mf][1][1] = Alo[k8 + t][r + 8];
                Af[mf][1][2] = Alo[k8 + t + 4][r]; Af[mf][1][3] = Alo[k8 + t + 4][r + 8];
            }
            uint32_t Bf[2][2][2];
            #pragma unroll
            for (int nf = 0; nf < 2; nf++) {
                int c = wn + nf * 8 + g;
                Bf[nf][0][0] = Bhi[k8 + t][c]; Bf[nf][0][1] = Bhi[k8 + t + 4][c];
                Bf[nf][1][0] = Blo[k8 + t][c]; Bf[nf][1][1] = Blo[k8 + t + 4][c];
            }
            #pragma unroll
            for (int mf = 0; mf < 2; mf++)
                #pragma unroll
                for (int nf = 0; nf < 2; nf++) {
                    MMA_TF32(acc[mf][nf], Af[mf][0], Bf[nf][0]);  // hi*hi
                    MMA_TF32(acc[mf][nf], Af[mf][0], Bf[nf][1]);  // hi*lo
                    MMA_TF32(acc[mf][nf], Af[mf][1], Bf[nf][0]);  // lo*hi
                }
        }
    }

    #pragma unroll
    for (int mf = 0; mf < 2; mf++)
        #pragma unroll
        for (int nf = 0; nf < 2; nf++) {
            int row = m0 + wm + mf * 16 + g;
            int col = n0 + wn + nf * 8 + t * 2;
            float b0 = bv[col], b1 = bv[col + 1];
            *(float2*)&C[row * A_DIM + col] =
                make_float2(acc[mf][nf][0] + b0, acc[mf][nf][1] + b1);
            *(float2*)&C[(row + 8) * A_DIM + col] =
                make_float2(acc[mf][nf][2] + b0, acc[mf][nf][3] + b1);
        }
}

// ---------------------------------------------------------------------------
// Kernel 2: att[n,p] = sum_a relu(att1[p,a] + att23[n,a] + att3[n,a]) * Wf[a]
// (bf cancels in softmax). 64n x 64p tile, 256 threads, 4x4 microtile.
// ---------------------------------------------------------------------------
#define CA 64
__global__ __launch_bounds__(256)
void att_main_kernel(const float* __restrict__ Wf)
{
    __shared__ float s1 [CA][68];   // [a][p]
    __shared__ float s23[CA][68];   // [a][n]
    __shared__ float sw[A_DIM];

    const int tid = threadIdx.x;
    const int tx  = tid & 15;
    const int ty  = tid >> 4;
    const int p0  = blockIdx.x * 64;
    const int n0  = blockIdx.y * 64;

    if (tid < A_DIM) sw[tid] = Wf[tid];

    float acc[4][4] = {};

    const int la = tid & 63;
    const int lr = tid >> 6;

    for (int a0 = 0; a0 < A_DIM; a0 += CA) {
        __syncthreads();
        #pragma unroll
        for (int i = 0; i < 16; i++) {
            int r = lr + 4 * i;
            s1 [la][r] = g_att1 [(p0 + r) * A_DIM + a0 + la];
            s23[la][r] = g_att23[(n0 + r) * A_DIM + a0 + la]
                       + g_att3 [(n0 + r) * A_DIM + a0 + la];
        }
        __syncthreads();

        #pragma unroll 8
        for (int a = 0; a < CA; a++) {
            float wa = sw[a0 + a];
            float4 r1 = *(const float4*)&s1 [a][tx * 4];
            float4 r2 = *(const float4*)&s23[a][ty * 4];
            float x1[4] = {r1.x, r1.y, r1.z, r1.w};
            float x2[4] = {r2.x, r2.y, r2.z, r2.w};
            #pragma unroll
            for (int j = 0; j < 4; j++)
                #pragma unroll
                for (int i = 0; i < 4; i++)
                    acc[j][i] += fmaxf(x1[i] + x2[j], 0.0f) * wa;
        }
    }

    #pragma unroll
    for (int j = 0; j < 4; j++) {
        float4 o = make_float4(acc[j][0], acc[j][1], acc[j][2], acc[j][3]);
        *(float4*)&g_att[(n0 + ty * 4 + j) * P_PIX + p0 + tx * 4] = o;
    }
}

// ---------------------------------------------------------------------------
// Kernel 3: row softmax over P -> alpha
// ---------------------------------------------------------------------------
__global__ __launch_bounds__(256)
void softmax_kernel(float* __restrict__ alpha)
{
    const int n   = blockIdx.x;
    const int tid = threadIdx.x;
    const float* row = g_att + n * P_PIX;

    __shared__ float wred[8];
    __shared__ float bm, bs;

    float x[4];
    float m = -1e30f;
    #pragma unroll
    for (int i = 0; i < 4; i++) {
        x[i] = row[tid + 256 * i];
        m = fmaxf(m, x[i]);
    }
    #pragma unroll
    for (int o = 16; o > 0; o >>= 1) m = fmaxf(m, __shfl_xor_sync(0xffffffffu, m, o));
    if ((tid & 31) == 0) wred[tid >> 5] = m;
    __syncthreads();
    if (tid == 0) {
        float v = wred[0];
        #pragma unroll
        for (int k = 1; k < 8; k++) v = fmaxf(v, wred[k]);
        bm = v;
    }
    __syncthreads();
    m = bm;

    float s = 0.0f;
    #pragma unroll
    for (int i = 0; i < 4; i++) {
        x[i] = __expf(x[i] - m);
        s += x[i];
    }
    #pragma unroll
    for (int o = 16; o > 0; o >>= 1) s += __shfl_xor_sync(0xffffffffu, s, o);
    __syncthreads();
    if ((tid & 31) == 0) wred[tid >> 5] = s;
    __syncthreads();
    if (tid == 0) {
        float v = 0.0f;
        #pragma unroll
        for (int k = 0; k < 8; k++) v += wred[k];
        bs = v;
    }
    __syncthreads();
    float inv = 1.0f / bs;

    #pragma unroll
    for (int i = 0; i < 4; i++)
        alpha[n * P_PIX + tid + 256 * i] = x[i] * inv;
}

// ---------------------------------------------------------------------------
// Kernel 4: tc_gemm_ab — awe = alpha @ enc  (M=1024, N=512, K=1024)
// Block 64x64, BK=32, 256 thr, warp tile 32m x 16n, 3x-TF32 split mma.
// B (enc) is already [K][N] row-major: staged directly.
// ---------------------------------------------------------------------------
__global__ __launch_bounds__(256)
void tc_gemm_ab(const float* __restrict__ A,   // alpha (N, P)
                const float* __restrict__ B,   // enc   (P, E)
                float* __restrict__ C)         // awe   (N, E)
{
    __shared__ uint32_t Ahi[32][68], Alo[32][68];
    __shared__ uint32_t Bhi[32][68], Blo[32][68];

    const int tid = threadIdx.x;
    const int m0  = blockIdx.y * 64;
    const int n0  = blockIdx.x * 64;

    const int am  = tid >> 2;          // 0..63
    const int akc = (tid & 3) * 8;
    const int bk  = tid >> 3;          // 0..31
    const int bnc = (tid & 7) * 8;

    const int lane = tid & 31, wid = tid >> 5;
    const int wm = (wid >> 2) * 32;
    const int wn = (wid & 3) * 16;
    const int g = lane >> 2, t = lane & 3;

    float acc[2][2][4] = {};

    float4 apre[2], bpre[2];
    apre[0] = *(const float4*)&A[(m0 + am) * P_PIX + akc];
    apre[1] = *(const float4*)&A[(m0 + am) * P_PIX + akc + 4];
    bpre[0] = *(const float4*)&B[bk * E_DIM + n0 + bnc];
    bpre[1] = *(const float4*)&B[bk * E_DIM + n0 + bnc + 4];

    for (int k0 = 0; k0 < P_PIX; k0 += 32) {
        if (k0 > 0) __syncthreads();
        #pragma unroll
        for (int q = 0; q < 2; q++) {
            float av[4] = {apre[q].x, apre[q].y, apre[q].z, apre[q].w};
            #pragma unroll
            for (int j = 0; j < 4; j++) {
                uint32_t h = f2tf(av[j]);
                Ahi[akc + 4 * q + j][am] = h;
                Alo[akc + 4 * q + j][am] = f2tf(av[j] - __uint_as_float(h));
            }
            float bw[4] = {bpre[q].x, bpre[q].y, bpre[q].z, bpre[q].w};
            uint4 hb, lb;
            hb.x = f2tf(bw[0]); lb.x = f2tf(bw[0] - __uint_as_float(hb.x));
            hb.y = f2tf(bw[1]); lb.y = f2tf(bw[1] - __uint_as_float(hb.y));
            hb.z = f2tf(bw[2]); lb.z = f2tf(bw[2] - __uint_as_float(hb.z));
            hb.w = f2tf(bw[3]); lb.w = f2tf(bw[3] - __uint_as_float(hb.w));
            *(uint4*)&Bhi[bk][bnc + 4 * q] = hb;
            *(uint4*)&Blo[bk][bnc + 4 * q] = lb;
        }
        __syncthreads();

        if (k0 + 32 < P_PIX) {
            apre[0] = *(const float4*)&A[(m0 + am) * P_PIX + k0 + 32 + akc];
            apre[1] = *(const float4*)&A[(m0 + am) * P_PIX + k0 + 36 + akc];
            bpre[0] = *(const float4*)&B[(k0 + 32 + bk) * E_DIM + n0 + bnc];
            bpre[1] = *(const float4*)&B[(k0 + 32 + bk) * E_DIM + n0 + bnc + 4];
        }

        #pragma unroll
        for (int ks = 0; ks < 4; ks++) {
            const int k8 = ks * 8;
            uint32_t Af[2][2][4];
            #pragma unroll
            for (int mf = 0; mf < 2; mf++) {
                int r = wm + mf * 16 + g;
                Af[mf][0][0] = Ahi[k8 + t][r];     Af[mf][0][1] = Ahi[k8 + t][r + 8];
                Af[mf][0][2] = Ahi[k8 + t + 4][r]; Af[mf][0][3] = Ahi[k8 + t + 4][r + 8];
                Af[mf][1][0] = Alo[k8 + t][r];     Af[mf][1][1] = Alo[k8 + t][r + 8];
                Af[mf][1][2] = Alo[k8 + t + 4][r]; Af[mf][1][3] = Alo[k8 + t + 4][r + 8];
            }
            uint32_t Bf[2][2][2];
            #pragma unroll
            for (int nf = 0; nf < 2; nf++) {
                int c = wn + nf * 8 + g;
                Bf[nf][0][0] = Bhi[k8 + t][c]; Bf[nf][0][1] = Bhi[k8 + t + 4][c];
                Bf[nf][1][0] = Blo[k8 + t][c]; Bf[nf][1][1] = Blo[k8 + t + 4][c];
            }
            #pragma unroll
            for (int mf = 0; mf < 2; mf++)
                #pragma unroll
                for (int nf = 0; nf < 2; nf++) {
                    MMA_TF32(acc[mf][nf], Af[mf][0], Bf[nf][0]);
                    MMA_TF32(acc[mf][nf], Af[mf][0], Bf[nf][1]);
                    MMA_TF32(acc[mf][nf], Af[mf][1], Bf[nf][0]);
                }
        }
    }

    #pragma unroll
    for (int mf = 0; mf < 2; mf++)
        #pragma unroll
        for (int nf = 0; nf < 2; nf++) {
            int row = m0 + wm + mf * 16 + g;
            int col = n0 + wn + nf * 8 + t * 2;
            *(float2*)&C[row * E_DIM + col] =
                make_float2(acc[mf][nf][0], acc[mf][nf][1]);
            *(float2*)&C[(row + 8) * E_DIM + col] =
                make_float2(acc[mf][nf][2], acc[mf][nf][3]);
        }
}

// ---------------------------------------------------------------------------
// Launch
// ---------------------------------------------------------------------------
extern "C" void kernel_launch(void* const* d_in, const int* in_sizes, int n_in,
                              void* d_out, int out_size)
{
    (void)in_sizes; (void)n_in; (void)out_size;
    const float* enc = (const float*)d_in[0];
    const float* dh  = (const float*)d_in[1];
    const float* lo  = (const float*)d_in[2];
    const float* We  = (const float*)d_in[3];
    const float* be  = (const float*)d_in[4];
    const float* Wt  = (const float*)d_in[5];
    const float* bt  = (const float*)d_in[6];
    const float* Wl  = (const float*)d_in[7];
    const float* bl  = (const float*)d_in[8];
    const float* Wf  = (const float*)d_in[9];
    // d_in[10] = bf: uniform shift, cancels in softmax.

    float* awe   = (float*)d_out;
    float* alpha = (float*)d_out + N_ROWS * E_DIM;

    dim3 g1(A_DIM / 64, 1024 / 64, 3);
    tc_attproj<<<g1, 256>>>(enc, We, be, dh, Wt, bt, lo, Wl, bl);

    dim3 g2(P_PIX / 64, N_ROWS / 64);
    att_main_kernel<<<g2, 256>>>(Wf);

    softmax_kernel<<<N_ROWS, 256>>>(alpha);

    dim3 g4(E_DIM / 64, N_ROWS / 64);
    tc_gemm_ab<<<g4, 256>>>(alpha, enc, awe);
}

// round 7
// speedup vs baseline: 1.4729x; 1.4729x over previous
#include <cuda_runtime.h>
#include <cuda_bf16.h>
#include <stdint.h>

#define N_ROWS 1024   // N
#define P_PIX  1024   // P
#define E_DIM  512    // ENC / TAG / LANG
#define A_DIM  256    // ATT

// Scratch
__device__ float g_att1 [P_PIX * A_DIM];    // (P, A)  enc@We^T + be
__device__ float g_att23[N_ROWS * A_DIM];   // (N, A)  dh@Wt^T + bt
__device__ float g_att3 [N_ROWS * A_DIM];   // (N, A)  lo@Wl^T + bl
__device__ float g_att  [N_ROWS * P_PIX];   // (N, P)

// ---- bf16 helpers ----
__device__ __forceinline__ uint32_t pack_bf16(__nv_bfloat16 a, __nv_bfloat16 b) {
    __nv_bfloat162 t; t.x = a; t.y = b;           // low half = a (even k)
    return *(uint32_t*)&t;
}

// split a k-pair (x0 even, x1 odd) into {hi-pair, lo-pair}
__device__ __forceinline__ uint2 split2(float x0, float x1) {
    __nv_bfloat16 h0 = __float2bfloat16_rn(x0);
    __nv_bfloat16 h1 = __float2bfloat16_rn(x1);
    float r0 = x0 - __bfloat162float(h0);
    float r1 = x1 - __bfloat162float(h1);
    uint2 o;
    o.x = pack_bf16(h0, h1);
    o.y = pack_bf16(__float2bfloat16_rn(r0), __float2bfloat16_rn(r1));
    return o;
}

#define MMA_BF16(d, a, b)                                                   \
  asm("mma.sync.aligned.m16n8k16.row.col.f32.bf16.bf16.f32 "                \
      "{%0,%1,%2,%3},{%4,%5,%6,%7},{%8,%9},{%0,%1,%2,%3};"                  \
      : "+f"(d[0]), "+f"(d[1]), "+f"(d[2]), "+f"(d[3])                      \
      : "r"(a[0]), "r"(a[1]), "r"(a[2]), "r"(a[3]), "r"(b[0]), "r"(b[1]))

#define SPAD 20   // uint2 stride: 40 words = 8 (mod 32) -> conflict-free frags

// ---------------------------------------------------------------------------
// Kernel 1: tc_attproj — C = A @ W^T + bias, per z-slice (M=1024, N=256, K=512)
// Block 64x64, BK=32, 256 thr, warp tile 32m x 16n, bf16 3-split k16 mma.
// ---------------------------------------------------------------------------
__global__ __launch_bounds__(256)
void tc_attproj(const float* __restrict__ enc, const float* __restrict__ We, const float* __restrict__ be,
                const float* __restrict__ dh,  const float* __restrict__ Wt, const float* __restrict__ bt,
                const float* __restrict__ lo,  const float* __restrict__ Wl, const float* __restrict__ bl)
{
    __shared__ uint2 Apk[64][SPAD];   // [m][kp] {hi2,lo2}
    __shared__ uint2 Bpk[64][SPAD];   // [n][kp]

    const int z = blockIdx.z;
    const float* A  = (z == 0) ? enc : (z == 1) ? dh : lo;
    const float* W  = (z == 0) ? We  : (z == 1) ? Wt : Wl;
    const float* bv = (z == 0) ? be  : (z == 1) ? bt : bl;
    float*       C  = (z == 0) ? g_att1 : (z == 1) ? g_att23 : g_att3;

    const int tid = threadIdx.x;
    const int m0  = blockIdx.y * 64;
    const int n0  = blockIdx.x * 64;

    const int row = tid >> 2;          // 0..63
    const int kc4 = tid & 3;           // k chunk (8 floats / 4 kp)

    const int lane = tid & 31, wid = tid >> 5;
    const int wm = (wid >> 2) * 32;    // 0 / 32
    const int wn = (wid & 3) * 16;     // 0/16/32/48
    const int g = lane >> 2, t = lane & 3;

    float acc[2][2][4] = {};

    float4 apre0 = *(const float4*)&A[(m0 + row) * E_DIM + kc4 * 8];
    float4 apre1 = *(const float4*)&A[(m0 + row) * E_DIM + kc4 * 8 + 4];
    float4 bpre0 = *(const float4*)&W[(n0 + row) * E_DIM + kc4 * 8];
    float4 bpre1 = *(const float4*)&W[(n0 + row) * E_DIM + kc4 * 8 + 4];

    for (int k0 = 0; k0 < E_DIM; k0 += 32) {
        if (k0 > 0) __syncthreads();
        Apk[row][kc4 * 4 + 0] = split2(apre0.x, apre0.y);
        Apk[row][kc4 * 4 + 1] = split2(apre0.z, apre0.w);
        Apk[row][kc4 * 4 + 2] = split2(apre1.x, apre1.y);
        Apk[row][kc4 * 4 + 3] = split2(apre1.z, apre1.w);
        Bpk[row][kc4 * 4 + 0] = split2(bpre0.x, bpre0.y);
        Bpk[row][kc4 * 4 + 1] = split2(bpre0.z, bpre0.w);
        Bpk[row][kc4 * 4 + 2] = split2(bpre1.x, bpre1.y);
        Bpk[row][kc4 * 4 + 3] = split2(bpre1.z, bpre1.w);
        __syncthreads();

        if (k0 + 32 < E_DIM) {
            apre0 = *(const float4*)&A[(m0 + row) * E_DIM + k0 + 32 + kc4 * 8];
            apre1 = *(const float4*)&A[(m0 + row) * E_DIM + k0 + 36 + kc4 * 8];
            bpre0 = *(const float4*)&W[(n0 + row) * E_DIM + k0 + 32 + kc4 * 8];
            bpre1 = *(const float4*)&W[(n0 + row) * E_DIM + k0 + 36 + kc4 * 8];
        }

        #pragma unroll
        for (int ks = 0; ks < 2; ks++) {
            const int kp0 = ks * 8;
            uint32_t Ah[2][4], Al[2][4];
            #pragma unroll
            for (int mf = 0; mf < 2; mf++) {
                int r = wm + mf * 16 + g;
                uint2 p00 = Apk[r][kp0 + t];
                uint2 p10 = Apk[r + 8][kp0 + t];
                uint2 p01 = Apk[r][kp0 + t + 4];
                uint2 p11 = Apk[r + 8][kp0 + t + 4];
                Ah[mf][0] = p00.x; Ah[mf][1] = p10.x; Ah[mf][2] = p01.x; Ah[mf][3] = p11.x;
                Al[mf][0] = p00.y; Al[mf][1] = p10.y; Al[mf][2] = p01.y; Al[mf][3] = p11.y;
            }
            uint32_t Bh[2][2], Bl[2][2];
            #pragma unroll
            for (int nf = 0; nf < 2; nf++) {
                int c = wn + nf * 8 + g;
                uint2 q0 = Bpk[c][kp0 + t];
                uint2 q1 = Bpk[c][kp0 + t + 4];
                Bh[nf][0] = q0.x; Bh[nf][1] = q1.x;
                Bl[nf][0] = q0.y; Bl[nf][1] = q1.y;
            }
            #pragma unroll
            for (int mf = 0; mf < 2; mf++)
                #pragma unroll
                for (int nf = 0; nf < 2; nf++) {
                    MMA_BF16(acc[mf][nf], Ah[mf], Bh[nf]);   // hi*hi
                    MMA_BF16(acc[mf][nf], Ah[mf], Bl[nf]);   // hi*lo
                    MMA_BF16(acc[mf][nf], Al[mf], Bh[nf]);   // lo*hi
                }
        }
    }

    #pragma unroll
    for (int mf = 0; mf < 2; mf++)
        #pragma unroll
        for (int nf = 0; nf < 2; nf++) {
            int r = m0 + wm + mf * 16 + g;
            int c = n0 + wn + nf * 8 + t * 2;
            float b0 = bv[c], b1 = bv[c + 1];
            *(float2*)&C[r * A_DIM + c] =
                make_float2(acc[mf][nf][0] + b0, acc[mf][nf][1] + b1);
            *(float2*)&C[(r + 8) * A_DIM + c] =
                make_float2(acc[mf][nf][2] + b0, acc[mf][nf][3] + b1);
        }
}

// ---------------------------------------------------------------------------
// Kernel 2: att[n,p] = sum_a relu(att1[p,a] + att23[n,a] + att3[n,a]) * Wf[a]
// (bf cancels in softmax). 64n x 64p tile, 256 threads, 4x4 microtile.
// ---------------------------------------------------------------------------
#define CA 64
__global__ __launch_bounds__(256)
void att_main_kernel(const float* __restrict__ Wf)
{
    __shared__ float s1 [CA][68];   // [a][p]
    __shared__ float s23[CA][68];   // [a][n]
    __shared__ float sw[A_DIM];

    const int tid = threadIdx.x;
    const int tx  = tid & 15;
    const int ty  = tid >> 4;
    const int p0  = blockIdx.x * 64;
    const int n0  = blockIdx.y * 64;

    if (tid < A_DIM) sw[tid] = Wf[tid];

    float acc[4][4] = {};

    const int la = tid & 63;
    const int lr = tid >> 6;

    for (int a0 = 0; a0 < A_DIM; a0 += CA) {
        __syncthreads();
        #pragma unroll
        for (int i = 0; i < 16; i++) {
            int r = lr + 4 * i;
            s1 [la][r] = g_att1 [(p0 + r) * A_DIM + a0 + la];
            s23[la][r] = g_att23[(n0 + r) * A_DIM + a0 + la]
                       + g_att3 [(n0 + r) * A_DIM + a0 + la];
        }
        __syncthreads();

        #pragma unroll 8
        for (int a = 0; a < CA; a++) {
            float wa = sw[a0 + a];
            float4 r1 = *(const float4*)&s1 [a][tx * 4];
            float4 r2 = *(const float4*)&s23[a][ty * 4];
            float x1[4] = {r1.x, r1.y, r1.z, r1.w};
            float x2[4] = {r2.x, r2.y, r2.z, r2.w};
            #pragma unroll
            for (int j = 0; j < 4; j++)
                #pragma unroll
                for (int i = 0; i < 4; i++)
                    acc[j][i] += fmaxf(x1[i] + x2[j], 0.0f) * wa;
        }
    }

    #pragma unroll
    for (int j = 0; j < 4; j++) {
        float4 o = make_float4(acc[j][0], acc[j][1], acc[j][2], acc[j][3]);
        *(float4*)&g_att[(n0 + ty * 4 + j) * P_PIX + p0 + tx * 4] = o;
    }
}

// ---------------------------------------------------------------------------
// Kernel 3: row softmax over P -> alpha
// ---------------------------------------------------------------------------
__global__ __launch_bounds__(256)
void softmax_kernel(float* __restrict__ alpha)
{
    const int n   = blockIdx.x;
    const int tid = threadIdx.x;
    const float* row = g_att + n * P_PIX;

    __shared__ float wred[8];
    __shared__ float bm, bs;

    float x[4];
    float m = -1e30f;
    #pragma unroll
    for (int i = 0; i < 4; i++) {
        x[i] = row[tid + 256 * i];
        m = fmaxf(m, x[i]);
    }
    #pragma unroll
    for (int o = 16; o > 0; o >>= 1) m = fmaxf(m, __shfl_xor_sync(0xffffffffu, m, o));
    if ((tid & 31) == 0) wred[tid >> 5] = m;
    __syncthreads();
    if (tid == 0) {
        float v = wred[0];
        #pragma unroll
        for (int k = 1; k < 8; k++) v = fmaxf(v, wred[k]);
        bm = v;
    }
    __syncthreads();
    m = bm;

    float s = 0.0f;
    #pragma unroll
    for (int i = 0; i < 4; i++) {
        x[i] = __expf(x[i] - m);
        s += x[i];
    }
    #pragma unroll
    for (int o = 16; o > 0; o >>= 1) s += __shfl_xor_sync(0xffffffffu, s, o);
    __syncthreads();
    if ((tid & 31) == 0) wred[tid >> 5] = s;
    __syncthreads();
    if (tid == 0) {
        float v = 0.0f;
        #pragma unroll
        for (int k = 0; k < 8; k++) v += wred[k];
        bs = v;
    }
    __syncthreads();
    float inv = 1.0f / bs;

    #pragma unroll
    for (int i = 0; i < 4; i++)
        alpha[n * P_PIX + tid + 256 * i] = x[i] * inv;
}

// ---------------------------------------------------------------------------
// Kernel 4: tc_gemm_ab — awe = alpha @ enc  (M=1024, N=512, K=1024)
// Block 64x64, BK=32, 256 thr, warp tile 32m x 16n, bf16 3-split k16 mma.
// B (enc) is [K][N] row-major: transposed into packed [n][kp] during staging.
// ---------------------------------------------------------------------------
__global__ __launch_bounds__(256)
void tc_gemm_ab(const float* __restrict__ A,   // alpha (N, P)
                const float* __restrict__ B,   // enc   (P, E)
                float* __restrict__ C)         // awe   (N, E)
{
    __shared__ uint2 Apk[64][SPAD];
    __shared__ uint2 Bpk[64][SPAD];

    const int tid = threadIdx.x;
    const int m0  = blockIdx.y * 64;
    const int n0  = blockIdx.x * 64;

    const int row = tid >> 2;          // A stager: 0..63
    const int kc4 = tid & 3;
    const int bn  = tid & 63;          // B stager: n
    const int bkg = tid >> 6;          // 0..3 -> kp group of 4

    const int lane = tid & 31, wid = tid >> 5;
    const int wm = (wid >> 2) * 32;
    const int wn = (wid & 3) * 16;
    const int g = lane >> 2, t = lane & 3;

    float acc[2][2][4] = {};

    float4 apre0 = *(const float4*)&A[(m0 + row) * P_PIX + kc4 * 8];
    float4 apre1 = *(const float4*)&A[(m0 + row) * P_PIX + kc4 * 8 + 4];
    float bpre[8];
    #pragma unroll
    for (int j = 0; j < 4; j++) {
        int k = (bkg * 4 + j) * 2;
        bpre[2 * j]     = B[k * E_DIM + n0 + bn];
        bpre[2 * j + 1] = B[(k + 1) * E_DIM + n0 + bn];
    }

    for (int k0 = 0; k0 < P_PIX; k0 += 32) {
        if (k0 > 0) __syncthreads();
        Apk[row][kc4 * 4 + 0] = split2(apre0.x, apre0.y);
        Apk[row][kc4 * 4 + 1] = split2(apre0.z, apre0.w);
        Apk[row][kc4 * 4 + 2] = split2(apre1.x, apre1.y);
        Apk[row][kc4 * 4 + 3] = split2(apre1.z, apre1.w);
        #pragma unroll
        for (int j = 0; j < 4; j++)
            Bpk[bn][bkg * 4 + j] = split2(bpre[2 * j], bpre[2 * j + 1]);
        __syncthreads();

        if (k0 + 32 < P_PIX) {
            apre0 = *(const float4*)&A[(m0 + row) * P_PIX + k0 + 32 + kc4 * 8];
            apre1 = *(const float4*)&A[(m0 + row) * P_PIX + k0 + 36 + kc4 * 8];
            #pragma unroll
            for (int j = 0; j < 4; j++) {
                int k = k0 + 32 + (bkg * 4 + j) * 2;
                bpre[2 * j]     = B[k * E_DIM + n0 + bn];
                bpre[2 * j + 1] = B[(k + 1) * E_DIM + n0 + bn];
            }
        }

        #pragma unroll
        for (int ks = 0; ks < 2; ks++) {
            const int kp0 = ks * 8;
            uint32_t Ah[2][4], Al[2][4];
            #pragma unroll
            for (int mf = 0; mf < 2; mf++) {
                int r = wm + mf * 16 + g;
                uint2 p00 = Apk[r][kp0 + t];
                uint2 p10 = Apk[r + 8][kp0 + t];
                uint2 p01 = Apk[r][kp0 + t + 4];
                uint2 p11 = Apk[r + 8][kp0 + t + 4];
                Ah[mf][0] = p00.x; Ah[mf][1] = p10.x; Ah[mf][2] = p01.x; Ah[mf][3] = p11.x;
                Al[mf][0] = p00.y; Al[mf][1] = p10.y; Al[mf][2] = p01.y; Al[mf][3] = p11.y;
            }
            uint32_t Bh[2][2], Bl[2][2];
            #pragma unroll
            for (int nf = 0; nf < 2; nf++) {
                int c = wn + nf * 8 + g;
                uint2 q0 = Bpk[c][kp0 + t];
                uint2 q1 = Bpk[c][kp0 + t + 4];
                Bh[nf][0] = q0.x; Bh[nf][1] = q1.x;
                Bl[nf][0] = q0.y; Bl[nf][1] = q1.y;
            }
            #pragma unroll
            for (int mf = 0; mf < 2; mf++)
                #pragma unroll
                for (int nf = 0; nf < 2; nf++) {
                    MMA_BF16(acc[mf][nf], Ah[mf], Bh[nf]);
                    MMA_BF16(acc[mf][nf], Ah[mf], Bl[nf]);
                    MMA_BF16(acc[mf][nf], Al[mf], Bh[nf]);
                }
        }
    }

    #pragma unroll
    for (int mf = 0; mf < 2; mf++)
        #pragma unroll
        for (int nf = 0; nf < 2; nf++) {
            int r = m0 + wm + mf * 16 + g;
            int c = n0 + wn + nf * 8 + t * 2;
            *(float2*)&C[r * E_DIM + c] =
                make_float2(acc[mf][nf][0], acc[mf][nf][1]);
            *(float2*)&C[(r + 8) * E_DIM + c] =
                make_float2(acc[mf][nf][2], acc[mf][nf][3]);
        }
}

// ---------------------------------------------------------------------------
// Launch
// ---------------------------------------------------------------------------
extern "C" void kernel_launch(void* const* d_in, const int* in_sizes, int n_in,
                              void* d_out, int out_size)
{
    (void)in_sizes; (void)n_in; (void)out_size;
    const float* enc = (const float*)d_in[0];
    const float* dh  = (const float*)d_in[1];
    const float* lo  = (const float*)d_in[2];
    const float* We  = (const float*)d_in[3];
    const float* be  = (const float*)d_in[4];
    const float* Wt  = (const float*)d_in[5];
    const float* bt  = (const float*)d_in[6];
    const float* Wl  = (const float*)d_in[7];
    const float* bl  = (const float*)d_in[8];
    const float* Wf  = (const float*)d_in[9];
    // d_in[10] = bf: uniform shift, cancels in softmax.

    float* awe   = (float*)d_out;
    float* alpha = (float*)d_out + N_ROWS * E_DIM;

    dim3 g1(A_DIM / 64, 1024 / 64, 3);
    tc_attproj<<<g1, 256>>>(enc, We, be, dh, Wt, bt, lo, Wl, bl);

    dim3 g2(P_PIX / 64, N_ROWS / 64);
    att_main_kernel<<<g2, 256>>>(Wf);

    softmax_kernel<<<N_ROWS, 256>>>(alpha);

    dim3 g4(E_DIM / 64, N_ROWS / 64);
    tc_gemm_ab<<<g4, 256>>>(alpha, enc, awe);
}

// round 8
// speedup vs baseline: 1.4764x; 1.0024x over previous
#include <cuda_runtime.h>
#include <cuda_bf16.h>
#include <stdint.h>

#define N_ROWS 1024   // N
#define P_PIX  1024   // P
#define E_DIM  512    // ENC / TAG / LANG
#define A_DIM  256    // ATT

// Scratch
__device__ float g_att1 [P_PIX * A_DIM];    // (P, A)  enc@We^T + be
__device__ float g_att23[N_ROWS * A_DIM];   // (N, A)  dh@Wt^T + bt
__device__ float g_att3 [N_ROWS * A_DIM];   // (N, A)  lo@Wl^T + bl
__device__ float g_att  [N_ROWS * P_PIX];   // (N, P)

// ---- bf16 helpers ----
__device__ __forceinline__ uint32_t pack_bf16(__nv_bfloat16 a, __nv_bfloat16 b) {
    __nv_bfloat162 t; t.x = a; t.y = b;           // low half = a (even k)
    return *(uint32_t*)&t;
}

// split a k-pair (x0 even, x1 odd) into {hi-pair, lo-pair}
__device__ __forceinline__ uint2 split2(float x0, float x1) {
    __nv_bfloat16 h0 = __float2bfloat16_rn(x0);
    __nv_bfloat16 h1 = __float2bfloat16_rn(x1);
    float r0 = x0 - __bfloat162float(h0);
    float r1 = x1 - __bfloat162float(h1);
    uint2 o;
    o.x = pack_bf16(h0, h1);
    o.y = pack_bf16(__float2bfloat16_rn(r0), __float2bfloat16_rn(r1));
    return o;
}

#define MMA_BF16(d, a, b)                                                   \
  asm("mma.sync.aligned.m16n8k16.row.col.f32.bf16.bf16.f32 "                \
      "{%0,%1,%2,%3},{%4,%5,%6,%7},{%8,%9},{%0,%1,%2,%3};"                  \
      : "+f"(d[0]), "+f"(d[1]), "+f"(d[2]), "+f"(d[3])                      \
      : "r"(a[0]), "r"(a[1]), "r"(a[2]), "r"(a[3]), "r"(b[0]), "r"(b[1]))

#define SPAD 20   // uint2 stride: 40 words = 8 (mod 32) -> conflict-free frags

// ---------------------------------------------------------------------------
// Kernel 1: tc_attproj — C = A @ W^T + bias, per z-slice (M=1024, N=256, K=512)
// Block 64x64, BK=32, 256 thr, warp tile 32m x 16n, bf16 3-split k16 mma.
// ---------------------------------------------------------------------------
__global__ __launch_bounds__(256)
void tc_attproj(const float* __restrict__ enc, const float* __restrict__ We, const float* __restrict__ be,
                const float* __restrict__ dh,  const float* __restrict__ Wt, const float* __restrict__ bt,
                const float* __restrict__ lo,  const float* __restrict__ Wl, const float* __restrict__ bl)
{
    __shared__ uint2 Apk[64][SPAD];   // [m][kp] {hi2,lo2}
    __shared__ uint2 Bpk[64][SPAD];   // [n][kp]

    const int z = blockIdx.z;
    const float* A  = (z == 0) ? enc : (z == 1) ? dh : lo;
    const float* W  = (z == 0) ? We  : (z == 1) ? Wt : Wl;
    const float* bv = (z == 0) ? be  : (z == 1) ? bt : bl;
    float*       C  = (z == 0) ? g_att1 : (z == 1) ? g_att23 : g_att3;

    const int tid = threadIdx.x;
    const int m0  = blockIdx.y * 64;
    const int n0  = blockIdx.x * 64;

    const int row = tid >> 2;          // 0..63
    const int kc4 = tid & 3;           // k chunk (8 floats / 4 kp)

    const int lane = tid & 31, wid = tid >> 5;
    const int wm = (wid >> 2) * 32;    // 0 / 32
    const int wn = (wid & 3) * 16;     // 0/16/32/48
    const int g = lane >> 2, t = lane & 3;

    float acc[2][2][4] = {};

    float4 apre0 = *(const float4*)&A[(m0 + row) * E_DIM + kc4 * 8];
    float4 apre1 = *(const float4*)&A[(m0 + row) * E_DIM + kc4 * 8 + 4];
    float4 bpre0 = *(const float4*)&W[(n0 + row) * E_DIM + kc4 * 8];
    float4 bpre1 = *(const float4*)&W[(n0 + row) * E_DIM + kc4 * 8 + 4];

    for (int k0 = 0; k0 < E_DIM; k0 += 32) {
        if (k0 > 0) __syncthreads();
        Apk[row][kc4 * 4 + 0] = split2(apre0.x, apre0.y);
        Apk[row][kc4 * 4 + 1] = split2(apre0.z, apre0.w);
        Apk[row][kc4 * 4 + 2] = split2(apre1.x, apre1.y);
        Apk[row][kc4 * 4 + 3] = split2(apre1.z, apre1.w);
        Bpk[row][kc4 * 4 + 0] = split2(bpre0.x, bpre0.y);
        Bpk[row][kc4 * 4 + 1] = split2(bpre0.z, bpre0.w);
        Bpk[row][kc4 * 4 + 2] = split2(bpre1.x, bpre1.y);
        Bpk[row][kc4 * 4 + 3] = split2(bpre1.z, bpre1.w);
        __syncthreads();

        if (k0 + 32 < E_DIM) {
            apre0 = *(const float4*)&A[(m0 + row) * E_DIM + k0 + 32 + kc4 * 8];
            apre1 = *(const float4*)&A[(m0 + row) * E_DIM + k0 + 36 + kc4 * 8];
            bpre0 = *(const float4*)&W[(n0 + row) * E_DIM + k0 + 32 + kc4 * 8];
            bpre1 = *(const float4*)&W[(n0 + row) * E_DIM + k0 + 36 + kc4 * 8];
        }

        #pragma unroll
        for (int ks = 0; ks < 2; ks++) {
            const int kp0 = ks * 8;
            uint32_t Ah[2][4], Al[2][4];
            #pragma unroll
            for (int mf = 0; mf < 2; mf++) {
                int r = wm + mf * 16 + g;
                uint2 p00 = Apk[r][kp0 + t];
                uint2 p10 = Apk[r + 8][kp0 + t];
                uint2 p01 = Apk[r][kp0 + t + 4];
                uint2 p11 = Apk[r + 8][kp0 + t + 4];
                Ah[mf][0] = p00.x; Ah[mf][1] = p10.x; Ah[mf][2] = p01.x; Ah[mf][3] = p11.x;
                Al[mf][0] = p00.y; Al[mf][1] = p10.y; Al[mf][2] = p01.y; Al[mf][3] = p11.y;
            }
            uint32_t Bh[2][2], Bl[2][2];
            #pragma unroll
            for (int nf = 0; nf < 2; nf++) {
                int c = wn + nf * 8 + g;
                uint2 q0 = Bpk[c][kp0 + t];
                uint2 q1 = Bpk[c][kp0 + t + 4];
                Bh[nf][0] = q0.x; Bh[nf][1] = q1.x;
                Bl[nf][0] = q0.y; Bl[nf][1] = q1.y;
            }
            #pragma unroll
            for (int mf = 0; mf < 2; mf++)
                #pragma unroll
                for (int nf = 0; nf < 2; nf++) {
                    MMA_BF16(acc[mf][nf], Ah[mf], Bh[nf]);   // hi*hi
                    MMA_BF16(acc[mf][nf], Ah[mf], Bl[nf]);   // hi*lo
                    MMA_BF16(acc[mf][nf], Al[mf], Bh[nf]);   // lo*hi
                }
        }
    }

    #pragma unroll
    for (int mf = 0; mf < 2; mf++)
        #pragma unroll
        for (int nf = 0; nf < 2; nf++) {
            int r = m0 + wm + mf * 16 + g;
            int c = n0 + wn + nf * 8 + t * 2;
            float b0 = bv[c], b1 = bv[c + 1];
            *(float2*)&C[r * A_DIM + c] =
                make_float2(acc[mf][nf][0] + b0, acc[mf][nf][1] + b1);
            *(float2*)&C[(r + 8) * A_DIM + c] =
                make_float2(acc[mf][nf][2] + b0, acc[mf][nf][3] + b1);
        }
}

// ---------------------------------------------------------------------------
// Kernel 2: att[n,p] = sum_a relu(att1[p,a] + att23[n,a] + att3[n,a]) * Wf[a]
// (bf cancels in softmax). 64n x 64p tile, 256 threads, 4x4 microtile.
// ---------------------------------------------------------------------------
#define CA 64
__global__ __launch_bounds__(256)
void att_main_kernel(const float* __restrict__ Wf)
{
    __shared__ float s1 [CA][68];   // [a][p]
    __shared__ float s23[CA][68];   // [a][n]
    __shared__ float sw[A_DIM];

    const int tid = threadIdx.x;
    const int tx  = tid & 15;
    const int ty  = tid >> 4;
    const int p0  = blockIdx.x * 64;
    const int n0  = blockIdx.y * 64;

    if (tid < A_DIM) sw[tid] = Wf[tid];

    float acc[4][4] = {};

    const int la = tid & 63;
    const int lr = tid >> 6;

    for (int a0 = 0; a0 < A_DIM; a0 += CA) {
        __syncthreads();
        #pragma unroll
        for (int i = 0; i < 16; i++) {
            int r = lr + 4 * i;
            s1 [la][r] = g_att1 [(p0 + r) * A_DIM + a0 + la];
            s23[la][r] = g_att23[(n0 + r) * A_DIM + a0 + la]
                       + g_att3 [(n0 + r) * A_DIM + a0 + la];
        }
        __syncthreads();

        #pragma unroll 8
        for (int a = 0; a < CA; a++) {
            float wa = sw[a0 + a];
            float4 r1 = *(const float4*)&s1 [a][tx * 4];
            float4 r2 = *(const float4*)&s23[a][ty * 4];
            float x1[4] = {r1.x, r1.y, r1.z, r1.w};
            float x2[4] = {r2.x, r2.y, r2.z, r2.w};
            #pragma unroll
            for (int j = 0; j < 4; j++)
                #pragma unroll
                for (int i = 0; i < 4; i++)
                    acc[j][i] += fmaxf(x1[i] + x2[j], 0.0f) * wa;
        }
    }

    #pragma unroll
    for (int j = 0; j < 4; j++) {
        float4 o = make_float4(acc[j][0], acc[j][1], acc[j][2], acc[j][3]);
        *(float4*)&g_att[(n0 + ty * 4 + j) * P_PIX + p0 + tx * 4] = o;
    }
}

// ---------------------------------------------------------------------------
// Kernel 3: row softmax over P -> alpha
// ---------------------------------------------------------------------------
__global__ __launch_bounds__(256)
void softmax_kernel(float* __restrict__ alpha)
{
    const int n   = blockIdx.x;
    const int tid = threadIdx.x;
    const float* row = g_att + n * P_PIX;

    __shared__ float wred[8];
    __shared__ float bm, bs;

    float x[4];
    float m = -1e30f;
    #pragma unroll
    for (int i = 0; i < 4; i++) {
        x[i] = row[tid + 256 * i];
        m = fmaxf(m, x[i]);
    }
    #pragma unroll
    for (int o = 16; o > 0; o >>= 1) m = fmaxf(m, __shfl_xor_sync(0xffffffffu, m, o));
    if ((tid & 31) == 0) wred[tid >> 5] = m;
    __syncthreads();
    if (tid == 0) {
        float v = wred[0];
        #pragma unroll
        for (int k = 1; k < 8; k++) v = fmaxf(v, wred[k]);
        bm = v;
    }
    __syncthreads();
    m = bm;

    float s = 0.0f;
    #pragma unroll
    for (int i = 0; i < 4; i++) {
        x[i] = __expf(x[i] - m);
        s += x[i];
    }
    #pragma unroll
    for (int o = 16; o > 0; o >>= 1) s += __shfl_xor_sync(0xffffffffu, s, o);
    __syncthreads();
    if ((tid & 31) == 0) wred[tid >> 5] = s;
    __syncthreads();
    if (tid == 0) {
        float v = 0.0f;
        #pragma unroll
        for (int k = 0; k < 8; k++) v += wred[k];
        bs = v;
    }
    __syncthreads();
    float inv = 1.0f / bs;

    #pragma unroll
    for (int i = 0; i < 4; i++)
        alpha[n * P_PIX + tid + 256 * i] = x[i] * inv;
}

// ---------------------------------------------------------------------------
// Kernel 4: tc_gemm_ab — awe = alpha @ enc  (M=1024, N=512, K=1024)
// Block 64x64, BK=32, 256 thr, warp tile 32m x 16n, bf16 3-split k16 mma.
// B (enc) is [K][N] row-major: transposed into packed [n][kp] during staging.
// ---------------------------------------------------------------------------
__global__ __launch_bounds__(256)
void tc_gemm_ab(const float* __restrict__ A,   // alpha (N, P)
                const float* __restrict__ B,   // enc   (P, E)
                float* __restrict__ C)         // awe   (N, E)
{
    __shared__ uint2 Apk[64][SPAD];
    __shared__ uint2 Bpk[64][SPAD];

    const int tid = threadIdx.x;
    const int m0  = blockIdx.y * 64;
    const int n0  = blockIdx.x * 64;

    const int row = tid >> 2;          // A stager: 0..63
    const int kc4 = tid & 3;
    const int bn  = tid & 63;          // B stager: n
    const int bkg = tid >> 6;          // 0..3 -> kp group of 4

    const int lane = tid & 31, wid = tid >> 5;
    const int wm = (wid >> 2) * 32;
    const int wn = (wid & 3) * 16;
    const int g = lane >> 2, t = lane & 3;

    float acc[2][2][4] = {};

    float4 apre0 = *(const float4*)&A[(m0 + row) * P_PIX + kc4 * 8];
    float4 apre1 = *(const float4*)&A[(m0 + row) * P_PIX + kc4 * 8 + 4];
    float bpre[8];
    #pragma unroll
    for (int j = 0; j < 4; j++) {
        int k = (bkg * 4 + j) * 2;
        bpre[2 * j]     = B[k * E_DIM + n0 + bn];
        bpre[2 * j + 1] = B[(k + 1) * E_DIM + n0 + bn];
    }

    for (int k0 = 0; k0 < P_PIX; k0 += 32) {
        if (k0 > 0) __syncthreads();
        Apk[row][kc4 * 4 + 0] = split2(apre0.x, apre0.y);
        Apk[row][kc4 * 4 + 1] = split2(apre0.z, apre0.w);
        Apk[row][kc4 * 4 + 2] = split2(apre1.x, apre1.y);
        Apk[row][kc4 * 4 + 3] = split2(apre1.z, apre1.w);
        #pragma unroll
        for (int j = 0; j < 4; j++)
            Bpk[bn][bkg * 4 + j] = split2(bpre[2 * j], bpre[2 * j + 1]);
        __syncthreads();

        if (k0 + 32 < P_PIX) {
            apre0 = *(const float4*)&A[(m0 + row) * P_PIX + k0 + 32 + kc4 * 8];
            apre1 = *(const float4*)&A[(m0 + row) * P_PIX + k0 + 36 + kc4 * 8];
            #pragma unroll
            for (int j = 0; j < 4; j++) {
                int k = k0 + 32 + (bkg * 4 + j) * 2;
                bpre[2 * j]     = B[k * E_DIM + n0 + bn];
                bpre[2 * j + 1] = B[(k + 1) * E_DIM + n0 + bn];
            }
        }

        #pragma unroll
        for (int ks = 0; ks < 2; ks++) {
            const int kp0 = ks * 8;
            uint32_t Ah[2][4], Al[2][4];
            #pragma unroll
            for (int mf = 0; mf < 2; mf++) {
                int r = wm + mf * 16 + g;
                uint2 p00 = Apk[r][kp0 + t];
                uint2 p10 = Apk[r + 8][kp0 + t];
                uint2 p01 = Apk[r][kp0 + t + 4];
                uint2 p11 = Apk[r + 8][kp0 + t + 4];
                Ah[mf][0] = p00.x; Ah[mf][1] = p10.x; Ah[mf][2] = p01.x; Ah[mf][3] = p11.x;
                Al[mf][0] = p00.y; Al[mf][1] = p10.y; Al[mf][2] = p01.y; Al[mf][3] = p11.y;
            }
            uint32_t Bh[2][2], Bl[2][2];
            #pragma unroll
            for (int nf = 0; nf < 2; nf++) {
                int c = wn + nf * 8 + g;
                uint2 q0 = Bpk[c][kp0 + t];
                uint2 q1 = Bpk[c][kp0 + t + 4];
                Bh[nf][0] = q0.x; Bh[nf][1] = q1.x;
                Bl[nf][0] = q0.y; Bl[nf][1] = q1.y;
            }
            #pragma unroll
            for (int mf = 0; mf < 2; mf++)
                #pragma unroll
                for (int nf = 0; nf < 2; nf++) {
                    MMA_BF16(acc[mf][nf], Ah[mf], Bh[nf]);
                    MMA_BF16(acc[mf][nf], Ah[mf], Bl[nf]);
                    MMA_BF16(acc[mf][nf], Al[mf], Bh[nf]);
                }
        }
    }

    #pragma unroll
    for (int mf = 0; mf < 2; mf++)
        #pragma unroll
        for (int nf = 0; nf < 2; nf++) {
            int r = m0 + wm + mf * 16 + g;
            int c = n0 + wn + nf * 8 + t * 2;
            *(float2*)&C[r * E_DIM + c] =
                make_float2(acc[mf][nf][0], acc[mf][nf][1]);
            *(float2*)&C[(r + 8) * E_DIM + c] =
                make_float2(acc[mf][nf][2], acc[mf][nf][3]);
        }
}

// ---------------------------------------------------------------------------
// Launch
// ---------------------------------------------------------------------------
extern "C" void kernel_launch(void* const* d_in, const int* in_sizes, int n_in,
                              void* d_out, int out_size)
{
    (void)in_sizes; (void)n_in; (void)out_size;
    const float* enc = (const float*)d_in[0];
    const float* dh  = (const float*)d_in[1];
    const float* lo  = (const float*)d_in[2];
    const float* We  = (const float*)d_in[3];
    const float* be  = (const float*)d_in[4];
    const float* Wt  = (const float*)d_in[5];
    const float* bt  = (const float*)d_in[6];
    const float* Wl  = (const float*)d_in[7];
    const float* bl  = (const float*)d_in[8];
    const float* Wf  = (const float*)d_in[9];
    // d_in[10] = bf: uniform shift, cancels in softmax.

    float* awe   = (float*)d_out;
    float* alpha = (float*)d_out + N_ROWS * E_DIM;

    dim3 g1(A_DIM / 64, 1024 / 64, 3);
    tc_attproj<<<g1, 256>>>(enc, We, be, dh, Wt, bt, lo, Wl, bl);

    dim3 g2(P_PIX / 64, N_ROWS / 64);
    att_main_kernel<<<g2, 256>>>(Wf);

    softmax_kernel<<<N_ROWS, 256>>>(alpha);

    dim3 g4(E_DIM / 64, N_ROWS / 64);
    tc_gemm_ab<<<g4, 256>>>(alpha, enc, awe);
}

// round 9
// speedup vs baseline: 1.6167x; 1.0951x over previous
#include <cuda_runtime.h>
#include <cuda_bf16.h>
#include <stdint.h>

#define N_ROWS 1024   // N
#define P_PIX  1024   // P
#define E_DIM  512    // ENC / TAG / LANG
#define A_DIM  256    // ATT

// fp32 scratch
__device__ float g_att1 [P_PIX * A_DIM];    // (P, A)  enc@We^T + be
__device__ float g_att23[N_ROWS * A_DIM];   // (N, A)  dh@Wt^T + bt
__device__ float g_att3 [N_ROWS * A_DIM];   // (N, A)  lo@Wl^T + bl
__device__ float g_att  [N_ROWS * P_PIX];   // (N, P)

// pre-split packed scratch: uint2 = {bf16x2 hi (k even,k odd), bf16x2 lo}
__device__ uint2 g_encA [P_PIX  * E_DIM / 2];   // [p][e/2]   pairs along e
__device__ uint2 g_dhA  [N_ROWS * E_DIM / 2];   // [n][e/2]
__device__ uint2 g_loA  [N_ROWS * E_DIM / 2];   // [n][e/2]
__device__ uint2 g_WeP  [A_DIM  * E_DIM / 2];   // [a][e/2]
__device__ uint2 g_WtP  [A_DIM  * E_DIM / 2];
__device__ uint2 g_WlP  [A_DIM  * E_DIM / 2];
__device__ uint2 g_encB [(P_PIX / 2) * E_DIM];  // [p/2][e]  pairs along p
__device__ uint2 g_alphaP[N_ROWS * P_PIX / 2];  // [n][p/2]  pairs along p

// ---- bf16 helpers ----
__device__ __forceinline__ uint32_t pack_bf16(__nv_bfloat16 a, __nv_bfloat16 b) {
    __nv_bfloat162 t; t.x = a; t.y = b;
    return *(uint32_t*)&t;
}
__device__ __forceinline__ uint2 split2(float x0, float x1) {
    __nv_bfloat16 h0 = __float2bfloat16_rn(x0);
    __nv_bfloat16 h1 = __float2bfloat16_rn(x1);
    float r0 = x0 - __bfloat162float(h0);
    float r1 = x1 - __bfloat162float(h1);
    uint2 o;
    o.x = pack_bf16(h0, h1);
    o.y = pack_bf16(__float2bfloat16_rn(r0), __float2bfloat16_rn(r1));
    return o;
}

#define MMA_BF16(d, a, b)                                                   \
  asm("mma.sync.aligned.m16n8k16.row.col.f32.bf16.bf16.f32 "                \
      "{%0,%1,%2,%3},{%4,%5,%6,%7},{%8,%9},{%0,%1,%2,%3};"                  \
      : "+f"(d[0]), "+f"(d[1]), "+f"(d[2]), "+f"(d[3])                      \
      : "r"(a[0]), "r"(a[1]), "r"(a[2]), "r"(a[3]), "r"(b[0]), "r"(b[1]))

__device__ __forceinline__ void cpa16(void* dst, const void* src) {
    uint32_t d = (uint32_t)__cvta_generic_to_shared(dst);
    asm volatile("cp.async.cg.shared.global [%0], [%1], 16;" :: "r"(d), "l"(src));
}
#define CP_COMMIT  asm volatile("cp.async.commit_group;")
#define CP_WAIT(n) asm volatile("cp.async.wait_group %0;" :: "n"(n))

#define SPAD 20   // uint2 row stride: 40 words = 8 mod 32 -> conflict-free

// ---------------------------------------------------------------------------
// Kernel 0: presplit — build packed bf16 hi/lo operand arrays.
//   z=0..2: enc/dh/lo (1024x512, pairs along last dim)
//   z=3..5: We/Wt/Wl  (256x512,  pairs along last dim)
//   z=6   : encB      (pairs across rows of enc: [p/2][e])
// ---------------------------------------------------------------------------
__global__ __launch_bounds__(256)
void presplit_kernel(const float* __restrict__ enc, const float* __restrict__ dh,
                     const float* __restrict__ lo,  const float* __restrict__ We,
                     const float* __restrict__ Wt,  const float* __restrict__ Wl)
{
    const int z   = blockIdx.z;
    const int idx = blockIdx.x * 256 + threadIdx.x;
    if (z < 6) {
        const float* X; uint2* Y; int count;
        switch (z) {
            case 0: X = enc; Y = g_encA; count = P_PIX  * E_DIM / 2; break;
            case 1: X = dh;  Y = g_dhA;  count = N_ROWS * E_DIM / 2; break;
            case 2: X = lo;  Y = g_loA;  count = N_ROWS * E_DIM / 2; break;
            case 3: X = We;  Y = g_WeP;  count = A_DIM  * E_DIM / 2; break;
            case 4: X = Wt;  Y = g_WtP;  count = A_DIM  * E_DIM / 2; break;
            default:X = (z == 4) ? Wt : Wl; Y = (z == 4) ? g_WtP : g_WlP;
                    count = A_DIM * E_DIM / 2; break;
        }
        if (idx < count) {
            float2 v = *(const float2*)&X[2 * idx];
            Y[idx] = split2(v.x, v.y);
        }
    } else {
        if (idx < (P_PIX / 2) * E_DIM) {
            int p2 = idx / E_DIM, e = idx % E_DIM;
            g_encB[idx] = split2(enc[(2 * p2) * E_DIM + e],
                                 enc[(2 * p2 + 1) * E_DIM + e]);
        }
    }
}

// ---------------------------------------------------------------------------
// Kernel 1: tc_attproj — C = A @ W^T + bias (M=1024, N=256, K=512), per z.
// Pre-split operands, cp.async double-buffered, bf16 3-split k16 mma.
// ---------------------------------------------------------------------------
__global__ __launch_bounds__(256)
void tc_attproj(const float* __restrict__ be, const float* __restrict__ bt,
                const float* __restrict__ bl)
{
    __shared__ uint2 Apk[2][64][SPAD];
    __shared__ uint2 Bpk[2][64][SPAD];

    const int z = blockIdx.z;
    const uint2* Asrc = (z == 0) ? g_encA : (z == 1) ? g_dhA : g_loA;
    const uint2* Bsrc = (z == 0) ? g_WeP  : (z == 1) ? g_WtP : g_WlP;
    const float* bv   = (z == 0) ? be     : (z == 1) ? bt    : bl;
    float*       C    = (z == 0) ? g_att1 : (z == 1) ? g_att23 : g_att3;

    const int tid = threadIdx.x;
    const int m0  = blockIdx.y * 64;
    const int n0  = blockIdx.x * 64;

    const int sr  = (tid * 2) >> 4;        // 0..31 base? (see op mapping below)
    (void)sr;

    const int lane = tid & 31, wid = tid >> 5;
    const int wm = (wid >> 2) * 32;
    const int wn = (wid & 3) * 16;
    const int g = lane >> 2, t = lane & 3;

    float acc[2][2][4] = {};

    const int KP_ROW = E_DIM / 2;          // uint2 per row

    // stage tile kt into buffer b (16 k-pairs)
    #define STAGE_P(kt, b)                                                   \
    {                                                                        \
        int kpb = (kt) * 16;                                                 \
        _Pragma("unroll")                                                    \
        for (int j = 0; j < 2; j++) {                                        \
            int o = tid + 256 * j;                                           \
            int r = o >> 3, kpc = (o & 7) * 2;                               \
            cpa16(&Apk[b][r][kpc], Asrc + (m0 + r) * KP_ROW + kpb + kpc);    \
            cpa16(&Bpk[b][r][kpc], Bsrc + (n0 + r) * KP_ROW + kpb + kpc);    \
        }                                                                    \
        CP_COMMIT;                                                           \
    }

    STAGE_P(0, 0);
    const int T = E_DIM / 32;              // 16 tiles
    for (int it = 0; it < T; it++) {
        const int b = it & 1;
        if (it + 1 < T) { STAGE_P(it + 1, (it + 1) & 1); CP_WAIT(1); }
        else           { CP_WAIT(0); }
        __syncthreads();

        #pragma unroll
        for (int ks = 0; ks < 2; ks++) {
            const int kp0 = ks * 8;
            uint32_t Ah[2][4], Al[2][4];
            #pragma unroll
            for (int mf = 0; mf < 2; mf++) {
                int r = wm + mf * 16 + g;
                uint2 p00 = Apk[b][r][kp0 + t];
                uint2 p10 = Apk[b][r + 8][kp0 + t];
                uint2 p01 = Apk[b][r][kp0 + t + 4];
                uint2 p11 = Apk[b][r + 8][kp0 + t + 4];
                Ah[mf][0] = p00.x; Ah[mf][1] = p10.x; Ah[mf][2] = p01.x; Ah[mf][3] = p11.x;
                Al[mf][0] = p00.y; Al[mf][1] = p10.y; Al[mf][2] = p01.y; Al[mf][3] = p11.y;
            }
            uint32_t Bh[2][2], Bl[2][2];
            #pragma unroll
            for (int nf = 0; nf < 2; nf++) {
                int c = wn + nf * 8 + g;
                uint2 q0 = Bpk[b][c][kp0 + t];
                uint2 q1 = Bpk[b][c][kp0 + t + 4];
                Bh[nf][0] = q0.x; Bh[nf][1] = q1.x;
                Bl[nf][0] = q0.y; Bl[nf][1] = q1.y;
            }
            #pragma unroll
            for (int mf = 0; mf < 2; mf++)
                #pragma unroll
                for (int nf = 0; nf < 2; nf++) {
                    MMA_BF16(acc[mf][nf], Ah[mf], Bh[nf]);
                    MMA_BF16(acc[mf][nf], Ah[mf], Bl[nf]);
                    MMA_BF16(acc[mf][nf], Al[mf], Bh[nf]);
                }
        }
        __syncthreads();
    }
    #undef STAGE_P

    #pragma unroll
    for (int mf = 0; mf < 2; mf++)
        #pragma unroll
        for (int nf = 0; nf < 2; nf++) {
            int r = m0 + wm + mf * 16 + g;
            int c = n0 + wn + nf * 8 + t * 2;
            float b0 = bv[c], b1 = bv[c + 1];
            *(float2*)&C[r * A_DIM + c] =
                make_float2(acc[mf][nf][0] + b0, acc[mf][nf][1] + b1);
            *(float2*)&C[(r + 8) * A_DIM + c] =
                make_float2(acc[mf][nf][2] + b0, acc[mf][nf][3] + b1);
        }
}

// ---------------------------------------------------------------------------
// Kernel 2: att[n,p] = sum_a relu(att1[p,a] + att23[n,a] + att3[n,a]) * Wf[a]
// ---------------------------------------------------------------------------
#define CA 64
__global__ __launch_bounds__(256)
void att_main_kernel(const float* __restrict__ Wf)
{
    __shared__ float s1 [CA][68];
    __shared__ float s23[CA][68];
    __shared__ float sw[A_DIM];

    const int tid = threadIdx.x;
    const int tx  = tid & 15;
    const int ty  = tid >> 4;
    const int p0  = blockIdx.x * 64;
    const int n0  = blockIdx.y * 64;

    if (tid < A_DIM) sw[tid] = Wf[tid];

    float acc[4][4] = {};

    const int la = tid & 63;
    const int lr = tid >> 6;

    for (int a0 = 0; a0 < A_DIM; a0 += CA) {
        __syncthreads();
        #pragma unroll
        for (int i = 0; i < 16; i++) {
            int r = lr + 4 * i;
            s1 [la][r] = g_att1 [(p0 + r) * A_DIM + a0 + la];
            s23[la][r] = g_att23[(n0 + r) * A_DIM + a0 + la]
                       + g_att3 [(n0 + r) * A_DIM + a0 + la];
        }
        __syncthreads();

        #pragma unroll 8
        for (int a = 0; a < CA; a++) {
            float wa = sw[a0 + a];
            float4 r1 = *(const float4*)&s1 [a][tx * 4];
            float4 r2 = *(const float4*)&s23[a][ty * 4];
            float x1[4] = {r1.x, r1.y, r1.z, r1.w};
            float x2[4] = {r2.x, r2.y, r2.z, r2.w};
            #pragma unroll
            for (int j = 0; j < 4; j++)
                #pragma unroll
                for (int i = 0; i < 4; i++)
                    acc[j][i] += fmaxf(x1[i] + x2[j], 0.0f) * wa;
        }
    }

    #pragma unroll
    for (int j = 0; j < 4; j++) {
        float4 o = make_float4(acc[j][0], acc[j][1], acc[j][2], acc[j][3]);
        *(float4*)&g_att[(n0 + ty * 4 + j) * P_PIX + p0 + tx * 4] = o;
    }
}

// ---------------------------------------------------------------------------
// Kernel 3: row softmax over P -> alpha (fp32) + packed split (g_alphaP)
// Each thread owns 4 consecutive p.
// ---------------------------------------------------------------------------
__global__ __launch_bounds__(256)
void softmax_kernel(float* __restrict__ alpha)
{
    const int n   = blockIdx.x;
    const int tid = threadIdx.x;

    __shared__ float wred[8];
    __shared__ float bm, bs;

    float4 xv = *(const float4*)&g_att[n * P_PIX + tid * 4];
    float x[4] = {xv.x, xv.y, xv.z, xv.w};

    float m = fmaxf(fmaxf(x[0], x[1]), fmaxf(x[2], x[3]));
    #pragma unroll
    for (int o = 16; o > 0; o >>= 1) m = fmaxf(m, __shfl_xor_sync(0xffffffffu, m, o));
    if ((tid & 31) == 0) wred[tid >> 5] = m;
    __syncthreads();
    if (tid == 0) {
        float v = wred[0];
        #pragma unroll
        for (int k = 1; k < 8; k++) v = fmaxf(v, wred[k]);
        bm = v;
    }
    __syncthreads();
    m = bm;

    float s = 0.0f;
    #pragma unroll
    for (int i = 0; i < 4; i++) {
        x[i] = __expf(x[i] - m);
        s += x[i];
    }
    #pragma unroll
    for (int o = 16; o > 0; o >>= 1) s += __shfl_xor_sync(0xffffffffu, s, o);
    __syncthreads();
    if ((tid & 31) == 0) wred[tid >> 5] = s;
    __syncthreads();
    if (tid == 0) {
        float v = 0.0f;
        #pragma unroll
        for (int k = 0; k < 8; k++) v += wred[k];
        bs = v;
    }
    __syncthreads();
    float inv = 1.0f / bs;

    float a0 = x[0] * inv, a1 = x[1] * inv, a2 = x[2] * inv, a3 = x[3] * inv;
    *(float4*)&alpha[n * P_PIX + tid * 4] = make_float4(a0, a1, a2, a3);

    uint2 s0 = split2(a0, a1);
    uint2 s1 = split2(a2, a3);
    uint4 pk; pk.x = s0.x; pk.y = s0.y; pk.z = s1.x; pk.w = s1.y;
    *(uint4*)&g_alphaP[n * (P_PIX / 2) + tid * 2] = pk;
}

// ---------------------------------------------------------------------------
// Kernel 4: tc_gemm_ab — awe = alpha @ enc  (M=1024, N=512, K=1024)
// A from g_alphaP [m][kp]; B from g_encB [kp][n]. cp.async double-buffered.
// ---------------------------------------------------------------------------
__global__ __launch_bounds__(256)
void tc_gemm_ab(float* __restrict__ C)
{
    __shared__ uint2 Apk[2][64][SPAD];
    __shared__ uint2 Bpk[2][16][68];

    const int tid = threadIdx.x;
    const int m0  = blockIdx.y * 64;
    const int n0  = blockIdx.x * 64;

    const int lane = tid & 31, wid = tid >> 5;
    const int wm = (wid >> 2) * 32;
    const int wn = (wid & 3) * 16;
    const int g = lane >> 2, t = lane & 3;

    float acc[2][2][4] = {};

    #define STAGE_G(kt, b)                                                    \
    {                                                                         \
        int kpb = (kt) * 16;                                                  \
        _Pragma("unroll")                                                     \
        for (int j = 0; j < 2; j++) {                                         \
            int o = tid + 256 * j;                                            \
            int r = o >> 3, kpc = (o & 7) * 2;                                \
            cpa16(&Apk[b][r][kpc],                                            \
                  g_alphaP + (m0 + r) * (P_PIX / 2) + kpb + kpc);             \
            int kp = o >> 5, nc = (o & 31) * 2;                               \
            cpa16(&Bpk[b][kp][nc], g_encB + (kpb + kp) * E_DIM + n0 + nc);    \
        }                                                                     \
        CP_COMMIT;                                                            \
    }

    STAGE_G(0, 0);
    const int T = P_PIX / 32;              // 32 tiles
    for (int it = 0; it < T; it++) {
        const int b = it & 1;
        if (it + 1 < T) { STAGE_G(it + 1, (it + 1) & 1); CP_WAIT(1); }
        else           { CP_WAIT(0); }
        __syncthreads();

        #pragma unroll
        for (int ks = 0; ks < 2; ks++) {
            const int kp0 = ks * 8;
            uint32_t Ah[2][4], Al[2][4];
            #pragma unroll
            for (int mf = 0; mf < 2; mf++) {
                int r = wm + mf * 16 + g;
                uint2 p00 = Apk[b][r][kp0 + t];
                uint2 p10 = Apk[b][r + 8][kp0 + t];
                uint2 p01 = Apk[b][r][kp0 + t + 4];
                uint2 p11 = Apk[b][r + 8][kp0 + t + 4];
                Ah[mf][0] = p00.x; Ah[mf][1] = p10.x; Ah[mf][2] = p01.x; Ah[mf][3] = p11.x;
                Al[mf][0] = p00.y; Al[mf][1] = p10.y; Al[mf][2] = p01.y; Al[mf][3] = p11.y;
            }
            uint32_t Bh[2][2], Bl[2][2];
            #pragma unroll
            for (int nf = 0; nf < 2; nf++) {
                int c = wn + nf * 8 + g;
                uint2 q0 = Bpk[b][kp0 + t][c];
                uint2 q1 = Bpk[b][kp0 + t + 4][c];
                Bh[nf][0] = q0.x; Bh[nf][1] = q1.x;
                Bl[nf][0] = q0.y; Bl[nf][1] = q1.y;
            }
            #pragma unroll
            for (int mf = 0; mf < 2; mf++)
                #pragma unroll
                for (int nf = 0; nf < 2; nf++) {
                    MMA_BF16(acc[mf][nf], Ah[mf], Bh[nf]);
                    MMA_BF16(acc[mf][nf], Ah[mf], Bl[nf]);
                    MMA_BF16(acc[mf][nf], Al[mf], Bh[nf]);
                }
        }
        __syncthreads();
    }
    #undef STAGE_G

    #pragma unroll
    for (int mf = 0; mf < 2; mf++)
        #pragma unroll
        for (int nf = 0; nf < 2; nf++) {
            int r = m0 + wm + mf * 16 + g;
            int c = n0 + wn + nf * 8 + t * 2;
            *(float2*)&C[r * E_DIM + c] =
                make_float2(acc[mf][nf][0], acc[mf][nf][1]);
            *(float2*)&C[(r + 8) * E_DIM + c] =
                make_float2(acc[mf][nf][2], acc[mf][nf][3]);
        }
}

// ---------------------------------------------------------------------------
// Launch
// ---------------------------------------------------------------------------
extern "C" void kernel_launch(void* const* d_in, const int* in_sizes, int n_in,
                              void* d_out, int out_size)
{
    (void)in_sizes; (void)n_in; (void)out_size;
    const float* enc = (const float*)d_in[0];
    const float* dh  = (const float*)d_in[1];
    const float* lo  = (const float*)d_in[2];
    const float* We  = (const float*)d_in[3];
    const float* be  = (const float*)d_in[4];
    const float* Wt  = (const float*)d_in[5];
    const float* bt  = (const float*)d_in[6];
    const float* Wl  = (const float*)d_in[7];
    const float* bl  = (const float*)d_in[8];
    const float* Wf  = (const float*)d_in[9];
    // d_in[10] = bf: uniform shift, cancels in softmax.

    float* awe   = (float*)d_out;
    float* alpha = (float*)d_out + N_ROWS * E_DIM;

    dim3 g0(1024, 1, 7);
    presplit_kernel<<<g0, 256>>>(enc, dh, lo, We, Wt, Wl);

    dim3 g1(A_DIM / 64, 1024 / 64, 3);
    tc_attproj<<<g1, 256>>>(be, bt, bl);

    dim3 g2(P_PIX / 64, N_ROWS / 64);
    att_main_kernel<<<g2, 256>>>(Wf);

    softmax_kernel<<<N_ROWS, 256>>>(alpha);

    dim3 g4(E_DIM / 64, N_ROWS / 64);
    tc_gemm_ab<<<g4, 256>>>(awe);
}